// round 4
// baseline (speedup 1.0000x reference)
#include <cuda_runtime.h>
#include <cuda_fp16.h>
#include <cstdint>

// Problem constants: N=100000, F_IN=512, F_OUT=128, nnz=1.6M each
#define F_OUT  128
#define NMAX   100000
#define CAP    64      // ELL row capacity; degrees ~Poisson(16), P(deg>=64) ~ 1e-18

// ---------- scratch (__device__ globals; allocation-free) ----------
__device__ __half g_base[(size_t)NMAX * F_OUT];        // intermediate [N,128] fp16 (25.6 MB)
__device__ int    d_deg_f[NMAX];
__device__ int    d_deg_a[NMAX];
__device__ int2   d_ell_f[(size_t)NMAX * CAP];         // packed {col, val_bits}
__device__ int2   d_ell_a[(size_t)NMAX * CAP];         // packed {src, val_bits}

// ---------- build ----------
__global__ void zero_deg_kernel(int n) {
    int stride = gridDim.x * blockDim.x;
    for (int i = blockIdx.x * blockDim.x + threadIdx.x; i < n; i += stride) {
        d_deg_f[i] = 0;
        d_deg_a[i] = 0;
    }
}

__global__ void build_ell_kernel(const int* __restrict__ f_rows,
                                 const int* __restrict__ f_cols,
                                 const float* __restrict__ f_vals, int fn,
                                 const int* __restrict__ a_dst,
                                 const int* __restrict__ a_src,
                                 const float* __restrict__ a_vals, int an) {
    int i = blockIdx.x * blockDim.x + threadIdx.x;
    if (i < fn) {
        int r = f_rows[i];
        int p = atomicAdd(&d_deg_f[r], 1);
        p = min(p, CAP - 1);                           // overflow guard (never hit)
        d_ell_f[(size_t)r * CAP + p] = make_int2(f_cols[i], __float_as_int(f_vals[i]));
    } else if (i < fn + an) {
        int j = i - fn;
        int r = a_dst[j];
        int p = atomicAdd(&d_deg_a[r], 1);
        p = min(p, CAP - 1);
        d_ell_a[(size_t)r * CAP + p] = make_int2(a_src[j], __float_as_int(a_vals[j]));
    }
}

// ---------- gather SpMMs (warp per node, no atomics, pipelined x4) ----------

// Step 1: base[node, :] = sum_j v_j * W[c_j, :]   (W 256 KB fp32, ~L1-resident)
__global__ void gemm_feat_kernel(const float4* __restrict__ W4, int n) {
    int node = (blockIdx.x * blockDim.x + threadIdx.x) >> 5;
    int lane = threadIdx.x & 31;
    if (node >= n) return;
    int deg = min(d_deg_f[node], CAP);
    const int2* __restrict__ ell = &d_ell_f[(size_t)node * CAP];

    float4 acc = make_float4(0.f, 0.f, 0.f, 0.f);
    int j = 0;
    for (; j + 4 <= deg; j += 4) {
        // 4 edges of metadata in two 16B broadcast loads
        int4 e01 = __ldg(reinterpret_cast<const int4*>(ell + j));
        int4 e23 = __ldg(reinterpret_cast<const int4*>(ell + j + 2));
        // issue all 4 row-gathers before consuming (MLP)
        float4 w0 = __ldg(&W4[((size_t)e01.x << 5) + lane]);
        float4 w1 = __ldg(&W4[((size_t)e01.z << 5) + lane]);
        float4 w2 = __ldg(&W4[((size_t)e23.x << 5) + lane]);
        float4 w3 = __ldg(&W4[((size_t)e23.z << 5) + lane]);
        float v0 = __int_as_float(e01.y), v1 = __int_as_float(e01.w);
        float v2 = __int_as_float(e23.y), v3 = __int_as_float(e23.w);
        acc.x += v0 * w0.x; acc.y += v0 * w0.y; acc.z += v0 * w0.z; acc.w += v0 * w0.w;
        acc.x += v1 * w1.x; acc.y += v1 * w1.y; acc.z += v1 * w1.z; acc.w += v1 * w1.w;
        acc.x += v2 * w2.x; acc.y += v2 * w2.y; acc.z += v2 * w2.z; acc.w += v2 * w2.w;
        acc.x += v3 * w3.x; acc.y += v3 * w3.y; acc.z += v3 * w3.z; acc.w += v3 * w3.w;
    }
    for (; j < deg; j++) {
        int2  t = __ldg(&ell[j]);
        float v = __int_as_float(t.y);
        float4 w = __ldg(&W4[((size_t)t.x << 5) + lane]);
        acc.x += v * w.x; acc.y += v * w.y; acc.z += v * w.z; acc.w += v * w.w;
    }
    __half2 h0 = __floats2half2_rn(acc.x, acc.y);
    __half2 h1 = __floats2half2_rn(acc.z, acc.w);
    uint2 u;
    u.x = *reinterpret_cast<unsigned*>(&h0);
    u.y = *reinterpret_cast<unsigned*>(&h1);
    reinterpret_cast<uint2*>(g_base)[((size_t)node << 5) + lane] = u;
}

__device__ __forceinline__ void fma_h2(float4& acc, float v, uint2 u) {
    __half2 h0 = *reinterpret_cast<const __half2*>(&u.x);
    __half2 h1 = *reinterpret_cast<const __half2*>(&u.y);
    float2 f0 = __half22float2(h0);
    float2 f1 = __half22float2(h1);
    acc.x += v * f0.x;  acc.y += v * f0.y;
    acc.z += v * f1.x;  acc.w += v * f1.y;
}

// Step 2: out[node, :] = sum_e v_e * base[src_e, :]  (base 25.6 MB fp16, L2-resident)
__global__ void gemm_adj_kernel(float4* __restrict__ out4, int n) {
    int node = (blockIdx.x * blockDim.x + threadIdx.x) >> 5;
    int lane = threadIdx.x & 31;
    if (node >= n) return;
    int deg = min(d_deg_a[node], CAP);
    const int2* __restrict__ ell = &d_ell_a[(size_t)node * CAP];
    const uint2* __restrict__ b2 = reinterpret_cast<const uint2*>(g_base);

    float4 acc = make_float4(0.f, 0.f, 0.f, 0.f);
    int j = 0;
    for (; j + 4 <= deg; j += 4) {
        int4 e01 = __ldg(reinterpret_cast<const int4*>(ell + j));
        int4 e23 = __ldg(reinterpret_cast<const int4*>(ell + j + 2));
        uint2 b0 = __ldg(&b2[((size_t)e01.x << 5) + lane]);
        uint2 b1 = __ldg(&b2[((size_t)e01.z << 5) + lane]);
        uint2 bb2 = __ldg(&b2[((size_t)e23.x << 5) + lane]);
        uint2 b3 = __ldg(&b2[((size_t)e23.z << 5) + lane]);
        fma_h2(acc, __int_as_float(e01.y), b0);
        fma_h2(acc, __int_as_float(e01.w), b1);
        fma_h2(acc, __int_as_float(e23.y), bb2);
        fma_h2(acc, __int_as_float(e23.w), b3);
    }
    for (; j < deg; j++) {
        int2  t = __ldg(&ell[j]);
        uint2 b = __ldg(&b2[((size_t)t.x << 5) + lane]);
        fma_h2(acc, __int_as_float(t.y), b);
    }
    out4[((size_t)node << 5) + lane] = acc;
}

// Inputs (metadata order):
//   d_in[0]: adj_indices  int32  [2 * N_EDGES]   (dst rows, then src cols)
//   d_in[1]: adj_values   fp32   [N_EDGES]
//   d_in[2]: feat_rows    int32  [FEAT_NNZ]
//   d_in[3]: feat_cols    int32  [FEAT_NNZ]
//   d_in[4]: feat_values  fp32   [FEAT_NNZ]
//   d_in[5]: weight       fp32   [F_IN * F_OUT]
//   d_in[6]: num_nodes    int32  [1]
// Output: fp32 [N, F_OUT]
extern "C" void kernel_launch(void* const* d_in, const int* in_sizes, int n_in,
                              void* d_out, int out_size) {
    const int*   adj_idx  = (const int*)  d_in[0];
    const float* adj_vals = (const float*)d_in[1];
    const int*   f_rows   = (const int*)  d_in[2];
    const int*   f_cols   = (const int*)  d_in[3];
    const float* f_vals   = (const float*)d_in[4];
    const float* weight   = (const float*)d_in[5];
    float*       out      = (float*)d_out;

    int n_edges   = in_sizes[1];
    int feat_nnz  = in_sizes[4];
    int num_nodes = out_size / F_OUT;

    zero_deg_kernel<<<256, 512>>>(num_nodes);

    int total = feat_nnz + n_edges;
    build_ell_kernel<<<(total + 255) / 256, 256>>>(f_rows, f_cols, f_vals, feat_nnz,
                                                   adj_idx, adj_idx + n_edges, adj_vals,
                                                   n_edges);

    int warp_blocks = (num_nodes * 32 + 255) / 256;
    gemm_feat_kernel<<<warp_blocks, 256>>>((const float4*)weight, num_nodes);
    gemm_adj_kernel<<<warp_blocks, 256>>>((float4*)out, num_nodes);
}

// round 5
// speedup vs baseline: 1.4450x; 1.4450x over previous
#include <cuda_runtime.h>
#include <cuda_fp16.h>
#include <cstdint>

// Problem constants: N=100000, F_IN=512, F_OUT=128, nnz=1.6M each
#define F_OUT  128
#define F_IN   512
#define NMAX   100000
#define CAP    64      // ELL row capacity; degrees ~Poisson(16), P(deg>=64) ~ 1e-18

// ---------- scratch (__device__ globals; allocation-free) ----------
__device__ __half g_base[(size_t)NMAX * F_OUT];        // intermediate [N,128] fp16 (25.6 MB)
__device__ __half g_wh[(size_t)F_IN * F_OUT];          // W in fp16 (128 KB, L1-resident)
__device__ int    d_deg_f[NMAX];
__device__ int    d_deg_a[NMAX];
__device__ int2   d_ell_f[(size_t)NMAX * CAP];         // packed {col, val_bits}
__device__ int2   d_ell_a[(size_t)NMAX * CAP];         // packed {src, val_bits}

// ---------- prep ----------
__global__ void zero_deg_kernel(int n) {
    int stride = gridDim.x * blockDim.x;
    for (int i = blockIdx.x * blockDim.x + threadIdx.x; i < n; i += stride) {
        d_deg_f[i] = 0;
        d_deg_a[i] = 0;
    }
}

// Convert W fp32 -> fp16 (65536 elements)
__global__ void w_half_kernel(const float2* __restrict__ w2) {
    int i = blockIdx.x * blockDim.x + threadIdx.x;   // over float2 pairs
    if (i >= (F_IN * F_OUT) / 2) return;
    float2 f = w2[i];
    reinterpret_cast<__half2*>(g_wh)[i] = __floats2half2_rn(f.x, f.y);
}

__global__ void build_ell_kernel(const int* __restrict__ f_rows,
                                 const int* __restrict__ f_cols,
                                 const float* __restrict__ f_vals, int fn,
                                 const int* __restrict__ a_dst,
                                 const int* __restrict__ a_src,
                                 const float* __restrict__ a_vals, int an) {
    int i = blockIdx.x * blockDim.x + threadIdx.x;
    if (i < fn) {
        int r = f_rows[i];
        int p = atomicAdd(&d_deg_f[r], 1);
        p = min(p, CAP - 1);                           // overflow guard (never hit)
        d_ell_f[(size_t)r * CAP + p] = make_int2(f_cols[i], __float_as_int(f_vals[i]));
    } else if (i < fn + an) {
        int j = i - fn;
        int r = a_dst[j];
        int p = atomicAdd(&d_deg_a[r], 1);
        p = min(p, CAP - 1);
        d_ell_a[(size_t)r * CAP + p] = make_int2(a_src[j], __float_as_int(a_vals[j]));
    }
}

// ---------- gather SpMMs (warp per node, no atomics, rolled loop) ----------

__device__ __forceinline__ void fma_h2(float4& acc, float v, uint2 u) {
    __half2 h0 = *reinterpret_cast<const __half2*>(&u.x);
    __half2 h1 = *reinterpret_cast<const __half2*>(&u.y);
    float2 f0 = __half22float2(h0);
    float2 f1 = __half22float2(h1);
    acc.x += v * f0.x;  acc.y += v * f0.y;
    acc.z += v * f1.x;  acc.w += v * f1.y;
}

// Step 1: base[node, :] = sum_j v_j * W[c_j, :]   (W fp16, 128 KB, L1-resident)
__global__ void gemm_feat_kernel(int n) {
    int node = (blockIdx.x * blockDim.x + threadIdx.x) >> 5;
    int lane = threadIdx.x & 31;
    if (node >= n) return;
    int deg = min(d_deg_f[node], CAP);
    const int2* __restrict__ ell = &d_ell_f[(size_t)node * CAP];
    const uint2* __restrict__ w2 = reinterpret_cast<const uint2*>(g_wh);

    float4 acc = make_float4(0.f, 0.f, 0.f, 0.f);
    for (int j = 0; j < deg; j++) {
        int2  t = __ldg(&ell[j]);                      // broadcast 8B
        float v = __int_as_float(t.y);
        uint2 w = __ldg(&w2[((size_t)t.x << 5) + lane]); // 8B/lane from L1-resident W
        fma_h2(acc, v, w);
    }
    __half2 h0 = __floats2half2_rn(acc.x, acc.y);
    __half2 h1 = __floats2half2_rn(acc.z, acc.w);
    uint2 u;
    u.x = *reinterpret_cast<unsigned*>(&h0);
    u.y = *reinterpret_cast<unsigned*>(&h1);
    reinterpret_cast<uint2*>(g_base)[((size_t)node << 5) + lane] = u;
}

// Step 2: out[node, :] = sum_e v_e * base[src_e, :]  (base 25.6 MB fp16, L2-resident)
__global__ void gemm_adj_kernel(float4* __restrict__ out4, int n) {
    int node = (blockIdx.x * blockDim.x + threadIdx.x) >> 5;
    int lane = threadIdx.x & 31;
    if (node >= n) return;
    int deg = min(d_deg_a[node], CAP);
    const int2* __restrict__ ell = &d_ell_a[(size_t)node * CAP];
    const uint2* __restrict__ b2 = reinterpret_cast<const uint2*>(g_base);

    float4 acc = make_float4(0.f, 0.f, 0.f, 0.f);
    for (int j = 0; j < deg; j++) {
        int2  t = __ldg(&ell[j]);
        float v = __int_as_float(t.y);
        uint2 b = __ldg(&b2[((size_t)t.x << 5) + lane]); // 8B/lane, 256B/warp coalesced
        fma_h2(acc, v, b);
    }
    out4[((size_t)node << 5) + lane] = acc;
}

// Inputs (metadata order):
//   d_in[0]: adj_indices  int32  [2 * N_EDGES]   (dst rows, then src cols)
//   d_in[1]: adj_values   fp32   [N_EDGES]
//   d_in[2]: feat_rows    int32  [FEAT_NNZ]
//   d_in[3]: feat_cols    int32  [FEAT_NNZ]
//   d_in[4]: feat_values  fp32   [FEAT_NNZ]
//   d_in[5]: weight       fp32   [F_IN * F_OUT]
//   d_in[6]: num_nodes    int32  [1]
// Output: fp32 [N, F_OUT]
extern "C" void kernel_launch(void* const* d_in, const int* in_sizes, int n_in,
                              void* d_out, int out_size) {
    const int*   adj_idx  = (const int*)  d_in[0];
    const float* adj_vals = (const float*)d_in[1];
    const int*   f_rows   = (const int*)  d_in[2];
    const int*   f_cols   = (const int*)  d_in[3];
    const float* f_vals   = (const float*)d_in[4];
    const float* weight   = (const float*)d_in[5];
    float*       out      = (float*)d_out;

    int n_edges   = in_sizes[1];
    int feat_nnz  = in_sizes[4];
    int num_nodes = out_size / F_OUT;

    zero_deg_kernel<<<256, 512>>>(num_nodes);
    w_half_kernel<<<(F_IN * F_OUT / 2 + 255) / 256, 256>>>((const float2*)weight);

    int total = feat_nnz + n_edges;
    build_ell_kernel<<<(total + 255) / 256, 256>>>(f_rows, f_cols, f_vals, feat_nnz,
                                                   adj_idx, adj_idx + n_edges, adj_vals,
                                                   n_edges);

    int warp_blocks = (num_nodes * 32 + 255) / 256;
    gemm_feat_kernel<<<warp_blocks, 256>>>(num_nodes);
    gemm_adj_kernel<<<warp_blocks, 256>>>((float4*)out, num_nodes);
}